// round 4
// baseline (speedup 1.0000x reference)
#include <cuda_runtime.h>
#include <math.h>

// ---------------------------------------------------------------------------
// SelectiveModel: B=32768, T=23, H=64, SLOTS=8, VOCAB=64.
//
// Structural collapse: gating MLP -> S[64][64] sigmoid table (recurrence is
// pure integer state); readout L1 -> QP/MP tables; only the 64x64 L2 GEMV
// remains as real FP work.
//
// R4: specialized kernel per phase:
//   K_rec : 1 thr/batch, integer-key argmax recurrence -> g_MT (8B/batch)
//   K_h   : 4 thr/batch gather+FMA -> g_HT k-major [64][B], coalesced
//   K_gemm: register-tiled FFMA2 GEMM HT @ rw2 -> out, 24 warps/SM
// ---------------------------------------------------------------------------

#define BTOT 32768

__device__ float g_S [64 * 64];
__device__ float g_QP[66 * 68];
__device__ float g_MP[64 * 68];
__device__ unsigned long long g_MT[BTOT];
__device__ float g_HT[64 * BTOT];          // k-major h

// ---------------- packed fp32x2 helpers -------------------------------------
__device__ __forceinline__ unsigned long long pk2(float lo, float hi) {
    unsigned long long r;
    asm("mov.b64 %0, {%1, %2};" : "=l"(r) : "f"(lo), "f"(hi));
    return r;
}
__device__ __forceinline__ void upk2(unsigned long long v, float& lo, float& hi) {
    asm("mov.b64 {%0, %1}, %2;" : "=f"(lo), "=f"(hi) : "l"(v));
}
__device__ __forceinline__ void fma2(unsigned long long& d,
                                     unsigned long long a, unsigned long long b) {
    asm("fma.rn.f32x2 %0, %1, %2, %0;" : "+l"(d) : "l"(a), "l"(b));
}

// ============================ K1: table precompute ==========================
__global__ void __launch_bounds__(128) precompute_kernel(
    const float* __restrict__ embed, const float* __restrict__ gw1,
    const float* __restrict__ gb1,   const float* __restrict__ gw2,
    const float* __restrict__ gb2,   const float* __restrict__ rw1,
    const float* __restrict__ rb1)
{
    const int bid = blockIdx.x, tid = threadIdx.x;
    if (bid < 64) {
        __shared__ float sEmb [64 * 65];
        __shared__ float sGw1 [128 * 32];
        __shared__ float sEdot[32];
        __shared__ float sMdot[64 * 33];
        for (int i = tid; i < 64 * 64; i += 128)
            sEmb[(i >> 6) * 65 + (i & 63)] = embed[i];
        for (int i = tid; i < 128 * 32; i += 128) sGw1[i] = gw1[i];
        __syncthreads();
        const int c = bid;
        if (tid < 32) {
            float acc = 0.f;
            #pragma unroll 16
            for (int k = 0; k < 64; k++) acc += sEmb[c * 65 + k] * sGw1[k * 32 + tid];
            sEdot[tid] = acc;
        }
        {
            const int m = tid & 63, half = tid >> 6;
            float acc[16];
            #pragma unroll
            for (int jj = 0; jj < 16; jj++) acc[jj] = 0.f;
            for (int k = 0; k < 64; k++) {
                const float e = sEmb[m * 65 + k];
                #pragma unroll
                for (int jj = 0; jj < 16; jj++)
                    acc[jj] += e * sGw1[(64 + k) * 32 + half * 16 + jj];
            }
            #pragma unroll
            for (int jj = 0; jj < 16; jj++) sMdot[m * 33 + half * 16 + jj] = acc[jj];
        }
        __syncthreads();
        if (tid < 64) {
            float acc = gb2[0];
            #pragma unroll
            for (int j = 0; j < 32; j++) {
                const float hv = sEdot[j] + sMdot[tid * 33 + j] + gb1[j];
                acc += fmaxf(hv, 0.f) * gw2[j];
            }
            g_S[c * 64 + tid] = 1.f / (1.f + expf(-acc));
        }
    } else if (bid < 97) {
        const int r = (bid - 64) * 2 + (tid >> 6);
        const int j = tid & 63;
        if (r < 66) {
            float acc = rb1[j];
            #pragma unroll 16
            for (int k = 0; k < 64; k++) acc += embed[r * 64 + k] * rw1[k * 64 + j];
            g_QP[r * 68 + j] = acc;
            if (j < 4) g_QP[r * 68 + 64 + j] = 0.f;
        }
    } else {
        const int r = (bid - 97) * 2 + (tid >> 6);
        const int j = tid & 63;
        float acc = 0.f;
        #pragma unroll 16
        for (int k = 0; k < 64; k++) acc += embed[r * 64 + k] * rw1[(64 + k) * 64 + j];
        g_MP[r * 68 + j] = acc;
        if (j < 4) g_MP[r * 68 + 64 + j] = 0.f;
    }
}

// ============================ K_rec: recurrence =============================
// grid 128 x 256, one thread per batch. Integer-key argmax:
//   key = (float_bits << 2) | (3 - (s&3));  sigmoid in (0,1] -> bits < 2^30,
//   so << 2 cannot overflow; larger idx bits = smaller s = first-max on ties.
//   Cross-half tie broken on score only (>>2) so lower half (smaller s) wins.
__global__ void __launch_bounds__(256) rec_kernel(const int* __restrict__ seqs32)
{
    __shared__ float sS[64 * 65];
    __shared__ unsigned char sTok[256 * 24];
    const int tid = threadIdx.x, bid = blockIdx.x;

    const int oddOr = seqs32[1] | seqs32[3] | seqs32[5] | seqs32[7] |
                      seqs32[9] | seqs32[11] | seqs32[13] | seqs32[15];
    const bool is64 = (oddOr == 0);

    for (int i = tid; i < 4096; i += 256)
        sS[(i >> 6) * 65 + (i & 63)] = g_S[i];
    const int base = bid * 256 * 24;
    for (int i = tid; i < 256 * 24; i += 256) {
        const int v = is64 ? seqs32[2 * (base + i)] : seqs32[base + i];
        sTok[i] = (unsigned char)v;
    }
    __syncthreads();

    const unsigned char* myTok = sTok + tid * 24;
    int mt[8];
    #pragma unroll
    for (int s = 0; s < 8; s++) mt[s] = myTok[s];

    #pragma unroll
    for (int t = 8; t < 23; t++) {
        const int c = myTok[t];
        const float* Srow = sS + c * 65;
        unsigned key[8];
        #pragma unroll
        for (int s = 0; s < 8; s++) {
            const unsigned bits = __float_as_uint(Srow[mt[s]]);
            key[s] = (bits << 2) | (unsigned)(3 - (s & 3));
        }
        const unsigned a0 = max(max(key[0], key[1]), max(key[2], key[3]));
        const unsigned a1 = max(max(key[4], key[5]), max(key[6], key[7]));
        // strict score compare across halves; tie -> low half (first index)
        const int bi = ((a1 >> 2) > (a0 >> 2)) ? (4 + 3 - (int)(a1 & 3))
                                               : (3 - (int)(a0 & 3));
        #pragma unroll
        for (int s = 0; s < 8; s++) if (bi == s) mt[s] = c;
    }

    unsigned long long pack = 0;
    #pragma unroll
    for (int s = 0; s < 8; s++)
        pack |= (unsigned long long)(unsigned)mt[s] << (8 * s);
    g_MT[bid * 256 + tid] = pack;
}

// ============================ K_h: h gather =================================
// grid 512 x 256; block = 64 batches x 4 j-quarters; warp = 32 batches, one jq.
__global__ void __launch_bounds__(256) h_kernel(const int* __restrict__ qtok32)
{
    __shared__ float sQP[66 * 68];
    __shared__ float sMP[64 * 68];
    const int tid = threadIdx.x, bid = blockIdx.x;

    {
        const float4* g = (const float4*)g_QP; float4* s = (float4*)sQP;
        for (int i = tid; i < 1122; i += 256) s[i] = g[i];
        g = (const float4*)g_MP; s = (float4*)sMP;
        for (int i = tid; i < 1088; i += 256) s[i] = g[i];
    }
    const int oddOr = qtok32[1] | qtok32[3] | qtok32[5] | qtok32[7] |
                      qtok32[9] | qtok32[11] | qtok32[13] | qtok32[15];
    const bool is64 = (oddOr == 0);

    const int w = tid >> 5, lane = tid & 31;
    const int jq = w >> 1;                    // j-quarter 0..3 (16 j's)
    const int bl = (w & 1) * 32 + lane;       // local batch 0..63
    const int b  = bid * 64 + bl;
    const int qt = is64 ? qtok32[2 * b] : qtok32[b];
    const unsigned long long pack = g_MT[b];
    __syncthreads();

    int moff[8];
    #pragma unroll
    for (int s = 0; s < 8; s++)
        moff[s] = (int)((pack >> (8 * s)) & 0xFF) * 68 + jq * 16;

    unsigned long long h[8];                  // 16 j's as 8 fp32x2 pairs
    {
        const float* qp = sQP + qt * 68 + jq * 16;
        #pragma unroll
        for (int i = 0; i < 4; i++) {
            const ulonglong2 q = *(const ulonglong2*)(qp + 4 * i);
            h[2 * i] = q.x; h[2 * i + 1] = q.y;
        }
    }
    const unsigned long long E2 = pk2(0.125f, 0.125f);
    #pragma unroll
    for (int s = 0; s < 8; s++) {
        const float* mp = sMP + moff[s];
        #pragma unroll
        for (int i = 0; i < 4; i++) {
            const ulonglong2 m = *(const ulonglong2*)(mp + 4 * i);
            fma2(h[2 * i],     m.x, E2);
            fma2(h[2 * i + 1], m.y, E2);
        }
    }
    // relu + k-major coalesced store (lane = consecutive batch)
    float* ht = g_HT + (jq * 16) * BTOT + b;
    #pragma unroll
    for (int i = 0; i < 8; i++) {
        float lo, hi; upk2(h[i], lo, hi);
        ht[(2 * i)     * BTOT] = fmaxf(lo, 0.f);
        ht[(2 * i + 1) * BTOT] = fmaxf(hi, 0.f);
    }
}

// ============================ K_gemm: HT @ rw2 ==============================
// grid 256 x 256; block tile 128 batches x 64 cols; thread tile 4b x 8c.
#define GEMM_SMEM_F (64 * 132 + 64 * 68 + 64)
#define GEMM_SMEM_B (GEMM_SMEM_F * 4)

__global__ void __launch_bounds__(256, 3) gemm_kernel(
    const float* __restrict__ rw2, const float* __restrict__ rb2,
    float* __restrict__ out)
{
    extern __shared__ float sm[];
    float* sHT = sm;                 // [64][132]
    float* sW  = sm + 64 * 132;      // [64][68]
    float* sRB = sW + 64 * 68;       // [64]
    const int tid = threadIdx.x, bid = blockIdx.x;
    const int b0 = bid * 128;

    // stage HT tile (coalesced per k-row) + re-padded W + bias
    for (int i = tid; i < 2048; i += 256) {
        const int r = i >> 5, c4 = i & 31;
        *(float4*)(sHT + r * 132 + c4 * 4) =
            *(const float4*)(g_HT + r * BTOT + b0 + c4 * 4);
    }
    {
        const float4* g = (const float4*)rw2;
        for (int i = tid; i < 1024; i += 256)
            ((float4*)sW)[(i >> 4) * 17 + (i & 15)] = g[i];
        if (tid < 16) ((float4*)sRB)[tid] = ((const float4*)rb2)[tid];
    }
    __syncthreads();

    const int w = tid >> 5, lane = tid & 31;
    const int bg = lane >> 3, cg = lane & 7;
    const float* hcol = sHT + w * 16 + bg * 4;     // + k*132
    const float* wrow = sW + cg * 8;               // + k*68

    unsigned long long acc[16];
    {
        const ulonglong2 r0 = *(const ulonglong2*)(sRB + cg * 8);
        const ulonglong2 r1 = *(const ulonglong2*)(sRB + cg * 8 + 4);
        #pragma unroll
        for (int b = 0; b < 4; b++) {
            acc[b * 4 + 0] = r0.x; acc[b * 4 + 1] = r0.y;
            acc[b * 4 + 2] = r1.x; acc[b * 4 + 3] = r1.y;
        }
    }
    #pragma unroll 4
    for (int k = 0; k < 64; k++) {
        const float4 hv = *(const float4*)(hcol + k * 132);
        const ulonglong2 wA = *(const ulonglong2*)(wrow + k * 68);
        const ulonglong2 wB = *(const ulonglong2*)(wrow + k * 68 + 4);
        unsigned long long hb;
        hb = pk2(hv.x, hv.x);
        fma2(acc[0],  hb, wA.x); fma2(acc[1],  hb, wA.y);
        fma2(acc[2],  hb, wB.x); fma2(acc[3],  hb, wB.y);
        hb = pk2(hv.y, hv.y);
        fma2(acc[4],  hb, wA.x); fma2(acc[5],  hb, wA.y);
        fma2(acc[6],  hb, wB.x); fma2(acc[7],  hb, wB.y);
        hb = pk2(hv.z, hv.z);
        fma2(acc[8],  hb, wA.x); fma2(acc[9],  hb, wA.y);
        fma2(acc[10], hb, wB.x); fma2(acc[11], hb, wB.y);
        hb = pk2(hv.w, hv.w);
        fma2(acc[12], hb, wA.x); fma2(acc[13], hb, wA.y);
        fma2(acc[14], hb, wB.x); fma2(acc[15], hb, wB.y);
    }

    const int gb0 = b0 + w * 16 + bg * 4;
    #pragma unroll
    for (int b = 0; b < 4; b++) {
        float* op = out + (gb0 + b) * 64 + cg * 8;
        float4 v0, v1;
        upk2(acc[b * 4 + 0], v0.x, v0.y); upk2(acc[b * 4 + 1], v0.z, v0.w);
        upk2(acc[b * 4 + 2], v1.x, v1.y); upk2(acc[b * 4 + 3], v1.z, v1.w);
        *(float4*)op = v0;
        *(float4*)(op + 4) = v1;
    }
}

// ============================== launch ======================================
extern "C" void kernel_launch(void* const* d_in, const int* in_sizes, int n_in,
                              void* d_out, int out_size)
{
    const int*   seqs  = (const int*)  d_in[0];
    const int*   qtok  = (const int*)  d_in[1];
    const float* embed = (const float*)d_in[2];
    const float* gw1   = (const float*)d_in[3];
    const float* gb1   = (const float*)d_in[4];
    const float* gw2   = (const float*)d_in[5];
    const float* gb2   = (const float*)d_in[6];
    const float* rw1   = (const float*)d_in[7];
    const float* rb1   = (const float*)d_in[8];
    const float* rw2   = (const float*)d_in[9];
    const float* rb2   = (const float*)d_in[10];

    cudaFuncSetAttribute(gemm_kernel,
                         cudaFuncAttributeMaxDynamicSharedMemorySize,
                         GEMM_SMEM_B);

    precompute_kernel<<<129, 128>>>(embed, gw1, gb1, gw2, gb2, rw1, rb1);
    rec_kernel<<<128, 256>>>(seqs);
    h_kernel<<<512, 256>>>(qtok);
    gemm_kernel<<<256, 256, GEMM_SMEM_B>>>(rw2, rb2, (float*)d_out);
}

// round 5
// speedup vs baseline: 1.0365x; 1.0365x over previous
#include <cuda_runtime.h>
#include <math.h>

// ---------------------------------------------------------------------------
// SelectiveModel: B=32768, T=23, H=64, SLOTS=8, VOCAB=64.
//
// Structural collapse: gating MLP -> S[64][64] sigmoid table (recurrence is
// pure integer state); readout L1 -> QP/MP tables; only the 64x64 L2 GEMM
// remains as real FP work.
//
// R5: 3 kernels.
//   precompute : S/QP/MP tables.
//   rh_kernel  : grid 512 x 256, 64 batches/block. Per-thread recurrence
//                (4-way SIMT dup over j-quarters, no barrier/handoff) +
//                h gather -> g_HT k-major, coalesced stores.
//   gemm_kernel: grid 512 x 256, 64 batches/block; warp 8b x 64c, thread
//                4b x 4c, packed fma.rn.f32x2. Grid now fills the chip.
// ---------------------------------------------------------------------------

#define BTOT 32768

__device__ float g_S [64 * 64];
__device__ float g_QP[66 * 68];
__device__ float g_MP[64 * 68];
__device__ float g_HT[64 * BTOT];          // k-major h

// ---------------- packed fp32x2 helpers -------------------------------------
__device__ __forceinline__ unsigned long long pk2(float lo, float hi) {
    unsigned long long r;
    asm("mov.b64 %0, {%1, %2};" : "=l"(r) : "f"(lo), "f"(hi));
    return r;
}
__device__ __forceinline__ void upk2(unsigned long long v, float& lo, float& hi) {
    asm("mov.b64 {%0, %1}, %2;" : "=f"(lo), "=f"(hi) : "l"(v));
}
__device__ __forceinline__ void fma2(unsigned long long& d,
                                     unsigned long long a, unsigned long long b) {
    asm("fma.rn.f32x2 %0, %1, %2, %0;" : "+l"(d) : "l"(a), "l"(b));
}

// ============================ K1: table precompute ==========================
__global__ void __launch_bounds__(128) precompute_kernel(
    const float* __restrict__ embed, const float* __restrict__ gw1,
    const float* __restrict__ gb1,   const float* __restrict__ gw2,
    const float* __restrict__ gb2,   const float* __restrict__ rw1,
    const float* __restrict__ rb1)
{
    const int bid = blockIdx.x, tid = threadIdx.x;
    if (bid < 64) {
        __shared__ float sEmb [64 * 65];
        __shared__ float sGw1 [128 * 32];
        __shared__ float sEdot[32];
        __shared__ float sMdot[64 * 33];
        for (int i = tid; i < 64 * 64; i += 128)
            sEmb[(i >> 6) * 65 + (i & 63)] = embed[i];
        for (int i = tid; i < 128 * 32; i += 128) sGw1[i] = gw1[i];
        __syncthreads();
        const int c = bid;
        if (tid < 32) {
            float acc = 0.f;
            #pragma unroll 16
            for (int k = 0; k < 64; k++) acc += sEmb[c * 65 + k] * sGw1[k * 32 + tid];
            sEdot[tid] = acc;
        }
        {
            const int m = tid & 63, half = tid >> 6;
            float acc[16];
            #pragma unroll
            for (int jj = 0; jj < 16; jj++) acc[jj] = 0.f;
            for (int k = 0; k < 64; k++) {
                const float e = sEmb[m * 65 + k];
                #pragma unroll
                for (int jj = 0; jj < 16; jj++)
                    acc[jj] += e * sGw1[(64 + k) * 32 + half * 16 + jj];
            }
            #pragma unroll
            for (int jj = 0; jj < 16; jj++) sMdot[m * 33 + half * 16 + jj] = acc[jj];
        }
        __syncthreads();
        if (tid < 64) {
            float acc = gb2[0];
            #pragma unroll
            for (int j = 0; j < 32; j++) {
                const float hv = sEdot[j] + sMdot[tid * 33 + j] + gb1[j];
                acc += fmaxf(hv, 0.f) * gw2[j];
            }
            g_S[c * 64 + tid] = 1.f / (1.f + expf(-acc));
        }
    } else if (bid < 97) {
        const int r = (bid - 64) * 2 + (tid >> 6);
        const int j = tid & 63;
        if (r < 66) {
            float acc = rb1[j];
            #pragma unroll 16
            for (int k = 0; k < 64; k++) acc += embed[r * 64 + k] * rw1[k * 64 + j];
            g_QP[r * 68 + j] = acc;
            if (j < 4) g_QP[r * 68 + 64 + j] = 0.f;
        }
    } else {
        const int r = (bid - 97) * 2 + (tid >> 6);
        const int j = tid & 63;
        float acc = 0.f;
        #pragma unroll 16
        for (int k = 0; k < 64; k++) acc += embed[r * 64 + k] * rw1[(64 + k) * 64 + j];
        g_MP[r * 68 + j] = acc;
        if (j < 4) g_MP[r * 68 + 64 + j] = 0.f;
    }
}

// ====================== K2: fused recurrence + h gather =====================
// grid 512 x 256; block = 64 batches. jq = tid>>6 (j-quarter), bl = tid&63.
// Each thread: full recurrence for its batch (SIMT-duplicated across the 4
// j-quarter threads -> no barrier, no handoff), then 16 h values -> g_HT.
#define RH_SMEM_BYTES ((64 * 65 + 66 * 68 + 64 * 68) * 4 + 64 * 24)

__global__ void __launch_bounds__(256, 4) rh_kernel(
    const int* __restrict__ seqs32, const int* __restrict__ qtok32)
{
    extern __shared__ float sm[];
    float* sS  = sm;                       // [64][65]
    float* sQP = sS + 64 * 65;             // [66][68]
    float* sMP = sQP + 66 * 68;            // [64][68]
    unsigned char* sTok = (unsigned char*)(sMP + 64 * 68);
    const int tid = threadIdx.x, bid = blockIdx.x;

    // int64 vs int32 token dtype detection (odd LE words of small int64 == 0)
    const int oddOr = seqs32[1] | seqs32[3] | seqs32[5] | seqs32[7] |
                      seqs32[9] | seqs32[11] | seqs32[13] | seqs32[15];
    const bool is64 = (oddOr == 0);

    for (int i = tid; i < 4096; i += 256)
        sS[(i >> 6) * 65 + (i & 63)] = g_S[i];
    {
        const float4* g = (const float4*)g_QP; float4* s = (float4*)sQP;
        for (int i = tid; i < 1122; i += 256) s[i] = g[i];
        g = (const float4*)g_MP; s = (float4*)sMP;
        for (int i = tid; i < 1088; i += 256) s[i] = g[i];
    }
    {
        const int base = bid * 64 * 24;
        for (int i = tid; i < 64 * 24; i += 256) {
            const int v = is64 ? seqs32[2 * (base + i)] : seqs32[base + i];
            sTok[i] = (unsigned char)v;
        }
    }
    const int jq = tid >> 6;               // 0..3  (same for whole warp)
    const int bl = tid & 63;               // lane-consecutive batches
    const int b  = bid * 64 + bl;
    const int qt = is64 ? qtok32[2 * b] : qtok32[b];
    __syncthreads();

    // ---- recurrence (integer-key argmax; validated in R4) ----
    int moff[8];
    {
        const unsigned char* myTok = sTok + bl * 24;
        int mt[8];
        #pragma unroll
        for (int s = 0; s < 8; s++) mt[s] = myTok[s];
        #pragma unroll
        for (int t = 8; t < 23; t++) {
            const int c = myTok[t];
            const float* Srow = sS + c * 65;
            unsigned key[8];
            #pragma unroll
            for (int s = 0; s < 8; s++) {
                const unsigned bits = __float_as_uint(Srow[mt[s]]);
                key[s] = (bits << 2) | (unsigned)(3 - (s & 3));
            }
            const unsigned a0 = max(max(key[0], key[1]), max(key[2], key[3]));
            const unsigned a1 = max(max(key[4], key[5]), max(key[6], key[7]));
            const int bi = ((a1 >> 2) > (a0 >> 2)) ? (4 + 3 - (int)(a1 & 3))
                                                   : (3 - (int)(a0 & 3));
            #pragma unroll
            for (int s = 0; s < 8; s++) if (bi == s) mt[s] = c;
        }
        #pragma unroll
        for (int s = 0; s < 8; s++) moff[s] = mt[s] * 68 + jq * 16;
    }

    // ---- h gather: this thread's 16 j's ----
    unsigned long long h[8];
    {
        const float* qp = sQP + qt * 68 + jq * 16;
        #pragma unroll
        for (int i = 0; i < 4; i++) {
            const ulonglong2 q = *(const ulonglong2*)(qp + 4 * i);
            h[2 * i] = q.x; h[2 * i + 1] = q.y;
        }
    }
    const unsigned long long E2 = pk2(0.125f, 0.125f);
    #pragma unroll
    for (int s = 0; s < 8; s++) {
        const float* mp = sMP + moff[s];
        #pragma unroll
        for (int i = 0; i < 4; i++) {
            const ulonglong2 m = *(const ulonglong2*)(mp + 4 * i);
            fma2(h[2 * i],     m.x, E2);
            fma2(h[2 * i + 1], m.y, E2);
        }
    }
    // relu + k-major store; warp = 32 consecutive b, same jq -> coalesced
    float* ht = g_HT + (jq * 16) * BTOT + b;
    #pragma unroll
    for (int i = 0; i < 8; i++) {
        float lo, hi; upk2(h[i], lo, hi);
        ht[(2 * i)     * BTOT] = fmaxf(lo, 0.f);
        ht[(2 * i + 1) * BTOT] = fmaxf(hi, 0.f);
    }
}

// ============================ K3: HT @ rw2 + rb2 ============================
// grid 512 x 256; block tile 64 batches x 64 cols; warp 8b x 64c; thread 4b x 4c.
#define GEMM_SMEM_BYTES ((64 * 68 * 2 + 64) * 4)

__global__ void __launch_bounds__(256) gemm_kernel(
    const float* __restrict__ rw2, const float* __restrict__ rb2,
    float* __restrict__ out)
{
    extern __shared__ float sm[];
    float* sHT = sm;                 // [64 k][68] (64 batches, padded)
    float* sW  = sm + 64 * 68;       // [64 k][68] (64 cols, padded)
    float* sRB = sW + 64 * 68;       // [64]
    const int tid = threadIdx.x, bid = blockIdx.x;
    const int b0 = bid * 64;

    for (int i = tid; i < 1024; i += 256) {
        const int r = i >> 4, c4 = i & 15;
        *(float4*)(sHT + r * 68 + c4 * 4) =
            *(const float4*)(g_HT + r * BTOT + b0 + c4 * 4);
        ((float4*)sW)[r * 17 + c4] = ((const float4*)rw2)[i];
    }
    if (tid < 16) ((float4*)sRB)[tid] = ((const float4*)rb2)[tid];
    __syncthreads();

    const int w = tid >> 5, lane = tid & 31;
    const int bg = lane >> 4;            // batch sub-group (0..1)
    const int cg = lane & 15;            // col group (0..15)
    const float* hrow = sHT + w * 8 + bg * 4;     // + k*68
    const float* wcol = sW + cg * 4;              // + k*68

    unsigned long long acc[8];           // 4 batches x (2 col-pairs)
    {
        const ulonglong2 r0 = *(const ulonglong2*)(sRB + cg * 4);
        #pragma unroll
        for (int b = 0; b < 4; b++) { acc[b * 2] = r0.x; acc[b * 2 + 1] = r0.y; }
    }
    #pragma unroll 8
    for (int k = 0; k < 64; k++) {
        const float4 hv      = *(const float4*)(hrow + k * 68);
        const ulonglong2 wv  = *(const ulonglong2*)(wcol + k * 68);
        unsigned long long hb;
        hb = pk2(hv.x, hv.x); fma2(acc[0], hb, wv.x); fma2(acc[1], hb, wv.y);
        hb = pk2(hv.y, hv.y); fma2(acc[2], hb, wv.x); fma2(acc[3], hb, wv.y);
        hb = pk2(hv.z, hv.z); fma2(acc[4], hb, wv.x); fma2(acc[5], hb, wv.y);
        hb = pk2(hv.w, hv.w); fma2(acc[6], hb, wv.x); fma2(acc[7], hb, wv.y);
    }

    const int gb0 = b0 + w * 8 + bg * 4;
    #pragma unroll
    for (int b = 0; b < 4; b++) {
        float4 v;
        upk2(acc[b * 2],     v.x, v.y);
        upk2(acc[b * 2 + 1], v.z, v.w);
        *(float4*)(out + (gb0 + b) * 64 + cg * 4) = v;
    }
}

// ============================== launch ======================================
extern "C" void kernel_launch(void* const* d_in, const int* in_sizes, int n_in,
                              void* d_out, int out_size)
{
    const int*   seqs  = (const int*)  d_in[0];
    const int*   qtok  = (const int*)  d_in[1];
    const float* embed = (const float*)d_in[2];
    const float* gw1   = (const float*)d_in[3];
    const float* gb1   = (const float*)d_in[4];
    const float* gw2   = (const float*)d_in[5];
    const float* gb2   = (const float*)d_in[6];
    const float* rw1   = (const float*)d_in[7];
    const float* rb1   = (const float*)d_in[8];
    const float* rw2   = (const float*)d_in[9];
    const float* rb2   = (const float*)d_in[10];

    cudaFuncSetAttribute(rh_kernel,
                         cudaFuncAttributeMaxDynamicSharedMemorySize,
                         RH_SMEM_BYTES);
    cudaFuncSetAttribute(gemm_kernel,
                         cudaFuncAttributeMaxDynamicSharedMemorySize,
                         GEMM_SMEM_BYTES);

    precompute_kernel<<<129, 128>>>(embed, gw1, gb1, gw2, gb2, rw1, rb1);
    rh_kernel<<<512, 256, RH_SMEM_BYTES>>>(seqs, qtok);
    gemm_kernel<<<512, 256, GEMM_SMEM_BYTES>>>(rw2, rb2, (float*)d_out);
}

// round 6
// speedup vs baseline: 1.0990x; 1.0603x over previous
#include <cuda_runtime.h>
#include <math.h>

// ---------------------------------------------------------------------------
// SelectiveModel: B=32768, T=23, H=64, SLOTS=8, VOCAB=64.
//
// Structural collapse: gating MLP -> S[64][64] sigmoid table (recurrence is
// pure integer state); readout L1 -> QP/MP tables; only the 64x64 L2 GEMM
// remains as real FP work.
//
// R6: 4 kernels, every phase chip-parallel:
//   P0  : all 12416 independent dot-64s (edot, mdot^T, QP, MP), 1 thr/dot.
//   P1  : S[c][m] combine + sigmoid (4096 entries, 1 thr/entry).
//   rh  : fused recurrence + h gather; duplicate-recurrence threads on
//         ADJACENT lanes (jq = tid&3) so their LDS dedups via broadcast.
//   gemm: 64x64 L2 GEMM, 64 batches/block, packed fma.rn.f32x2.
// ---------------------------------------------------------------------------

#define BTOT 32768

__device__ float g_S  [64 * 64];
__device__ float g_QP [66 * 68];
__device__ float g_MP [64 * 68];
__device__ float g_ED [64 * 32];     // edot[c][j]
__device__ float g_MDT[32 * 64];     // mdot transposed [j][m]
__device__ float g_HT [64 * BTOT];   // k-major h

// ---------------- packed fp32x2 helpers -------------------------------------
__device__ __forceinline__ unsigned long long pk2(float lo, float hi) {
    unsigned long long r;
    asm("mov.b64 %0, {%1, %2};" : "=l"(r) : "f"(lo), "f"(hi));
    return r;
}
__device__ __forceinline__ void upk2(unsigned long long v, float& lo, float& hi) {
    asm("mov.b64 {%0, %1}, %2;" : "=f"(lo), "=f"(hi) : "l"(v));
}
__device__ __forceinline__ void fma2(unsigned long long& d,
                                     unsigned long long a, unsigned long long b) {
    asm("fma.rn.f32x2 %0, %1, %2, %0;" : "+l"(d) : "l"(a), "l"(b));
}

// ===================== P0: all independent dot products =====================
// grid 49 x 256. Entry map:
//   [0,4096)      : ED/MDT  (r = e>>5 in 0..127, j = e&31)
//   [4096,8320)   : QP rows (r in 0..65, j in 0..63), includes rb1
//   [8320,12416)  : MP rows (r in 0..63, j in 0..63)
__global__ void __launch_bounds__(256) p0_kernel(
    const float* __restrict__ embed, const float* __restrict__ gw1,
    const float* __restrict__ rw1,   const float* __restrict__ rb1)
{
    const int idx = blockIdx.x * 256 + threadIdx.x;
    if (idx < 4096) {
        const int r = idx >> 5, j = idx & 31;
        const float* e = embed + (r & 63) * 64;
        const float* w = gw1 + ((r >> 6) * 64) * 32 + j;
        float a0 = 0.f, a1 = 0.f, a2 = 0.f, a3 = 0.f;
        #pragma unroll
        for (int k = 0; k < 64; k += 4) {
            a0 += e[k]     * w[k * 32];
            a1 += e[k + 1] * w[(k + 1) * 32];
            a2 += e[k + 2] * w[(k + 2) * 32];
            a3 += e[k + 3] * w[(k + 3) * 32];
        }
        const float acc = (a0 + a1) + (a2 + a3);
        if (r < 64) g_ED[r * 32 + j] = acc;          // edot[c][j]
        else        g_MDT[j * 64 + (r - 64)] = acc;  // mdot^T[j][m]
    } else if (idx < 8320) {
        const int e2 = idx - 4096;
        const int r = e2 >> 6, j = e2 & 63;
        const float* e = embed + r * 64;
        const float* w = rw1 + j;
        float a0 = rb1[j], a1 = 0.f, a2 = 0.f, a3 = 0.f;
        #pragma unroll
        for (int k = 0; k < 64; k += 4) {
            a0 += e[k]     * w[k * 64];
            a1 += e[k + 1] * w[(k + 1) * 64];
            a2 += e[k + 2] * w[(k + 2) * 64];
            a3 += e[k + 3] * w[(k + 3) * 64];
        }
        g_QP[r * 68 + j] = (a0 + a1) + (a2 + a3);
        if (j < 4) g_QP[r * 68 + 64 + j] = 0.f;
    } else if (idx < 12416) {
        const int e2 = idx - 8320;
        const int r = e2 >> 6, j = e2 & 63;
        const float* e = embed + r * 64;
        const float* w = rw1 + 64 * 64 + j;
        float a0 = 0.f, a1 = 0.f, a2 = 0.f, a3 = 0.f;
        #pragma unroll
        for (int k = 0; k < 64; k += 4) {
            a0 += e[k]     * w[k * 64];
            a1 += e[k + 1] * w[(k + 1) * 64];
            a2 += e[k + 2] * w[(k + 2) * 64];
            a3 += e[k + 3] * w[(k + 3) * 64];
        }
        g_MP[r * 68 + j] = (a0 + a1) + (a2 + a3);
        if (j < 4) g_MP[r * 68 + 64 + j] = 0.f;
    }
}

// ===================== P1: S table combine + sigmoid ========================
// grid 16 x 256; thread = one (c, m) entry.
__global__ void __launch_bounds__(256) p1_kernel(
    const float* __restrict__ gb1, const float* __restrict__ gw2,
    const float* __restrict__ gb2)
{
    const int idx = blockIdx.x * 256 + threadIdx.x;
    const int c = idx >> 6, m = idx & 63;
    const float* ed = g_ED + c * 32;        // uniform per warp-half
    float acc = gb2[0];
    #pragma unroll
    for (int j = 0; j < 32; j++) {
        const float hv = ed[j] + g_MDT[j * 64 + m] + gb1[j];   // MDT coalesced
        acc += fmaxf(hv, 0.f) * gw2[j];
    }
    g_S[c * 64 + m] = 1.f / (1.f + expf(-acc));
}

// ====================== rh: fused recurrence + h gather =====================
// grid 512 x 256; block = 64 batches. jq = tid&3, bl = tid>>2 so the 4
// threads duplicating one batch's recurrence are adjacent lanes -> their
// identical smem loads dedup via broadcast.
#define RH_SMEM_BYTES ((64 * 65 + 66 * 68 + 64 * 68) * 4 + 64 * 24)

__global__ void __launch_bounds__(256, 4) rh_kernel(
    const int* __restrict__ seqs32, const int* __restrict__ qtok32)
{
    extern __shared__ float sm[];
    float* sS  = sm;                       // [64][65]
    float* sQP = sS + 64 * 65;             // [66][68]
    float* sMP = sQP + 66 * 68;            // [64][68]
    unsigned char* sTok = (unsigned char*)(sMP + 64 * 68);
    const int tid = threadIdx.x, bid = blockIdx.x;

    // int64 vs int32 token dtype detection (odd LE words of small int64 == 0)
    const int oddOr = seqs32[1] | seqs32[3] | seqs32[5] | seqs32[7] |
                      seqs32[9] | seqs32[11] | seqs32[13] | seqs32[15];
    const bool is64 = (oddOr == 0);

    for (int i = tid; i < 4096; i += 256)
        sS[(i >> 6) * 65 + (i & 63)] = g_S[i];
    {
        const float4* g = (const float4*)g_QP; float4* s = (float4*)sQP;
        for (int i = tid; i < 1122; i += 256) s[i] = g[i];
        g = (const float4*)g_MP; s = (float4*)sMP;
        for (int i = tid; i < 1088; i += 256) s[i] = g[i];
    }
    {
        const int base = bid * 64 * 24;
        for (int i = tid; i < 64 * 24; i += 256) {
            const int v = is64 ? seqs32[2 * (base + i)] : seqs32[base + i];
            sTok[i] = (unsigned char)v;
        }
    }
    const int jq = tid & 3;                // j-quarter: adjacent lanes differ
    const int bl = tid >> 2;               // local batch 0..63
    const int b  = bid * 64 + bl;
    const int qt = is64 ? qtok32[2 * b] : qtok32[b];
    __syncthreads();

    // ---- recurrence (integer-key argmax; validated R4/R5) ----
    int moff[8];
    {
        const unsigned char* myTok = sTok + bl * 24;
        int mt[8];
        #pragma unroll
        for (int s = 0; s < 8; s++) mt[s] = myTok[s];
        #pragma unroll
        for (int t = 8; t < 23; t++) {
            const int c = myTok[t];
            const float* Srow = sS + c * 65;
            unsigned key[8];
            #pragma unroll
            for (int s = 0; s < 8; s++) {
                const unsigned bits = __float_as_uint(Srow[mt[s]]);
                key[s] = (bits << 2) | (unsigned)(3 - (s & 3));
            }
            const unsigned a0 = max(max(key[0], key[1]), max(key[2], key[3]));
            const unsigned a1 = max(max(key[4], key[5]), max(key[6], key[7]));
            const int bi = ((a1 >> 2) > (a0 >> 2)) ? (4 + 3 - (int)(a1 & 3))
                                                   : (3 - (int)(a0 & 3));
            #pragma unroll
            for (int s = 0; s < 8; s++) if (bi == s) mt[s] = c;
        }
        #pragma unroll
        for (int s = 0; s < 8; s++) moff[s] = mt[s] * 68 + jq * 16;
    }

    // ---- h gather: this thread's 16 j's ----
    unsigned long long h[8];
    {
        const float* qp = sQP + qt * 68 + jq * 16;
        #pragma unroll
        for (int i = 0; i < 4; i++) {
            const ulonglong2 q = *(const ulonglong2*)(qp + 4 * i);
            h[2 * i] = q.x; h[2 * i + 1] = q.y;
        }
    }
    const unsigned long long E2 = pk2(0.125f, 0.125f);
    #pragma unroll
    for (int s = 0; s < 8; s++) {
        const float* mp = sMP + moff[s];
        #pragma unroll
        for (int i = 0; i < 4; i++) {
            const ulonglong2 m = *(const ulonglong2*)(mp + 4 * i);
            fma2(h[2 * i],     m.x, E2);
            fma2(h[2 * i + 1], m.y, E2);
        }
    }
    // relu + k-major store; each (row, 8-consecutive-batch) = full 32B sector
    float* ht = g_HT + (jq * 16) * BTOT + b;
    #pragma unroll
    for (int i = 0; i < 8; i++) {
        float lo, hi; upk2(h[i], lo, hi);
        ht[(2 * i)     * BTOT] = fmaxf(lo, 0.f);
        ht[(2 * i + 1) * BTOT] = fmaxf(hi, 0.f);
    }
}

// ============================ gemm: HT @ rw2 + rb2 ==========================
// grid 512 x 256; block tile 64 batches x 64 cols; warp 8b x 64c; thread 4b x 4c.
#define GEMM_SMEM_BYTES ((64 * 68 * 2 + 64) * 4)

__global__ void __launch_bounds__(256) gemm_kernel(
    const float* __restrict__ rw2, const float* __restrict__ rb2,
    float* __restrict__ out)
{
    extern __shared__ float sm[];
    float* sHT = sm;                 // [64 k][68] (64 batches, padded)
    float* sW  = sm + 64 * 68;       // [64 k][68] (64 cols, padded)
    float* sRB = sW + 64 * 68;       // [64]
    const int tid = threadIdx.x, bid = blockIdx.x;
    const int b0 = bid * 64;

    for (int i = tid; i < 1024; i += 256) {
        const int r = i >> 4, c4 = i & 15;
        *(float4*)(sHT + r * 68 + c4 * 4) =
            *(const float4*)(g_HT + r * BTOT + b0 + c4 * 4);
        ((float4*)sW)[r * 17 + c4] = ((const float4*)rw2)[i];
    }
    if (tid < 16) ((float4*)sRB)[tid] = ((const float4*)rb2)[tid];
    __syncthreads();

    const int w = tid >> 5, lane = tid & 31;
    const int bg = lane >> 4;            // batch sub-group (0..1)
    const int cg = lane & 15;            // col group (0..15)
    const float* hrow = sHT + w * 8 + bg * 4;     // + k*68
    const float* wcol = sW + cg * 4;              // + k*68

    unsigned long long acc[8];           // 4 batches x (2 col-pairs)
    {
        const ulonglong2 r0 = *(const ulonglong2*)(sRB + cg * 4);
        #pragma unroll
        for (int b = 0; b < 4; b++) { acc[b * 2] = r0.x; acc[b * 2 + 1] = r0.y; }
    }
    #pragma unroll 8
    for (int k = 0; k < 64; k++) {
        const float4 hv      = *(const float4*)(hrow + k * 68);
        const ulonglong2 wv  = *(const ulonglong2*)(wcol + k * 68);
        unsigned long long hb;
        hb = pk2(hv.x, hv.x); fma2(acc[0], hb, wv.x); fma2(acc[1], hb, wv.y);
        hb = pk2(hv.y, hv.y); fma2(acc[2], hb, wv.x); fma2(acc[3], hb, wv.y);
        hb = pk2(hv.z, hv.z); fma2(acc[4], hb, wv.x); fma2(acc[5], hb, wv.y);
        hb = pk2(hv.w, hv.w); fma2(acc[6], hb, wv.x); fma2(acc[7], hb, wv.y);
    }

    const int gb0 = b0 + w * 8 + bg * 4;
    #pragma unroll
    for (int b = 0; b < 4; b++) {
        float4 v;
        upk2(acc[b * 2],     v.x, v.y);
        upk2(acc[b * 2 + 1], v.z, v.w);
        *(float4*)(out + (gb0 + b) * 64 + cg * 4) = v;
    }
}

// ============================== launch ======================================
extern "C" void kernel_launch(void* const* d_in, const int* in_sizes, int n_in,
                              void* d_out, int out_size)
{
    const int*   seqs  = (const int*)  d_in[0];
    const int*   qtok  = (const int*)  d_in[1];
    const float* embed = (const float*)d_in[2];
    const float* gw1   = (const float*)d_in[3];
    const float* gb1   = (const float*)d_in[4];
    const float* gw2   = (const float*)d_in[5];
    const float* gb2   = (const float*)d_in[6];
    const float* rw1   = (const float*)d_in[7];
    const float* rb1   = (const float*)d_in[8];
    const float* rw2   = (const float*)d_in[9];
    const float* rb2   = (const float*)d_in[10];

    cudaFuncSetAttribute(rh_kernel,
                         cudaFuncAttributeMaxDynamicSharedMemorySize,
                         RH_SMEM_BYTES);
    cudaFuncSetAttribute(gemm_kernel,
                         cudaFuncAttributeMaxDynamicSharedMemorySize,
                         GEMM_SMEM_BYTES);

    p0_kernel<<<49, 256>>>(embed, gw1, rw1, rb1);
    p1_kernel<<<16, 256>>>(gb1, gw2, gb2);
    rh_kernel<<<512, 256, RH_SMEM_BYTES>>>(seqs, qtok);
    gemm_kernel<<<512, 256, GEMM_SMEM_BYTES>>>(rw2, rb2, (float*)d_out);
}